// round 3
// baseline (speedup 1.0000x reference)
#include <cuda_runtime.h>

#define N_NODES 100000
#define E_MAX   1600000
#define NB      98
#define NPAD    (NB * 1024)   // 100352 >= N_NODES
#define FULL    0xFFFFFFFFu

// Scratch (allocation-free __device__ globals)
__device__ float g_t1[N_NODES * 64];     // feature @ W1
__device__ float g_g2[N_NODES * 16];     // relu(agg1+b1) @ W2
__device__ int   g_counts[NPAD];         // in-degree histogram (padded, zeroed)
__device__ int   g_offsets[NPAD];        // exclusive prefix sum
__device__ int   g_cursor[NPAD];         // fill cursors
__device__ int   g_blockTotal[NB];
__device__ int   g_edge_src[E_MAX];      // CSR: src ids grouped by dst

// K1: t1 = feature @ W1 (warp per row, W1 in smem). Also zeroes g_counts.
__global__ void k1_gemm1(const float* __restrict__ feat, const float* __restrict__ W1) {
    int gtid = blockIdx.x * blockDim.x + threadIdx.x;
    if (gtid < NPAD) g_counts[gtid] = 0;
    __shared__ float Ws[64 * 64];
    for (int i = threadIdx.x; i < 64 * 64; i += blockDim.x) Ws[i] = W1[i];
    __syncthreads();
    int row  = gtid >> 5;
    int lane = threadIdx.x & 31;
    if (row >= N_NODES) return;
    const float* f = feat + row * 64;
    float f_lo = f[lane];
    float f_hi = f[lane + 32];
    float acc0 = 0.f, acc1 = 0.f;
#pragma unroll
    for (int k = 0; k < 32; k++) {
        float a = __shfl_sync(FULL, f_lo, k);
        acc0 += a * Ws[k * 64 + lane];
        acc1 += a * Ws[k * 64 + 32 + lane];
    }
#pragma unroll
    for (int k = 0; k < 32; k++) {
        float a = __shfl_sync(FULL, f_hi, k);
        acc0 += a * Ws[(k + 32) * 64 + lane];
        acc1 += a * Ws[(k + 32) * 64 + 32 + lane];
    }
    g_t1[row * 64 + lane]      = acc0;
    g_t1[row * 64 + 32 + lane] = acc1;
}

// CSR: in-degree histogram.
__global__ void k_hist(const int* __restrict__ dst, int E) {
    int e = blockIdx.x * blockDim.x + threadIdx.x;
    if (e < E) atomicAdd(&g_counts[dst[e]], 1);
}

// CSR: per-1024-chunk totals.
__global__ void k_passA() {
    __shared__ int sh[256];
    int b = blockIdx.x, t = threadIdx.x;
    int sum = 0;
#pragma unroll
    for (int i = 0; i < 4; i++) sum += g_counts[b * 1024 + t + i * 256];
    sh[t] = sum;
    __syncthreads();
    for (int s = 128; s > 0; s >>= 1) {
        if (t < s) sh[t] += sh[t + s];
        __syncthreads();
    }
    if (t == 0) g_blockTotal[b] = sh[0];
}

// CSR: per-chunk scan; chunk base computed by summing prior blockTotals (98 ints, trivial).
__global__ void k_passC() {
    __shared__ int sh[1024];
    __shared__ int base;
    int b = blockIdx.x, t = threadIdx.x;
    if (t == 0) {
        int run = 0;
        for (int i = 0; i < b; i++) run += g_blockTotal[i];
        base = run;
    }
    int idx = b * 1024 + t;
    int c = g_counts[idx];
    sh[t] = c;
    __syncthreads();
    for (int d = 1; d < 1024; d <<= 1) {
        int v = (t >= d) ? sh[t - d] : 0;
        __syncthreads();
        sh[t] += v;
        __syncthreads();
    }
    int off = base + sh[t] - c;   // exclusive
    g_offsets[idx] = off;
    g_cursor[idx]  = off;
}

// CSR: scatter src ids grouped by dst.
__global__ void k_fill(const int* __restrict__ src, const int* __restrict__ dst, int E) {
    int e = blockIdx.x * blockDim.x + threadIdx.x;
    if (e < E) {
        int d = dst[e];
        int pos = atomicAdd(&g_cursor[d], 1);
        g_edge_src[pos] = src[e];
    }
}

// K_agg1: warp per node. Two 16-lane halves each gather a different edge's 64-float
// row via float4 (16 x 16B = 256B), unrolled x2. Then relu(+b1) @ W2 -> g2.
__global__ void k_agg1_fused(const float* __restrict__ b1, const float* __restrict__ W2) {
    __shared__ float W2s[64 * 16];
    __shared__ float b1s[64];
    __shared__ float hbuf[8][64];            // 8 warps/block
    for (int i = threadIdx.x; i < 64 * 16; i += blockDim.x) W2s[i] = W2[i];
    if (threadIdx.x < 64) b1s[threadIdx.x] = b1[threadIdx.x];
    __syncthreads();
    int n    = (blockIdx.x * blockDim.x + threadIdx.x) >> 5;
    int lane = threadIdx.x & 31;
    int w    = threadIdx.x >> 5;
    if (n >= N_NODES) return;

    int start = g_offsets[n];
    int deg   = g_counts[n];
    int half  = lane >> 4;                   // which edge of the pair
    int l16   = lane & 15;                   // float4 slot within row
    const float4* t1v = (const float4*)g_t1; // row = 16 float4
    float4 acc = make_float4(0.f, 0.f, 0.f, 0.f);

    int j = half;
    for (; j + 2 < deg; j += 4) {
        int s0 = __ldg(&g_edge_src[start + j]);
        int s1 = __ldg(&g_edge_src[start + j + 2]);
        float4 v0 = __ldg(&t1v[s0 * 16 + l16]);
        float4 v1 = __ldg(&t1v[s1 * 16 + l16]);
        acc.x += v0.x + v1.x; acc.y += v0.y + v1.y;
        acc.z += v0.z + v1.z; acc.w += v0.w + v1.w;
    }
    if (j < deg) {
        int s0 = __ldg(&g_edge_src[start + j]);
        float4 v0 = __ldg(&t1v[s0 * 16 + l16]);
        acc.x += v0.x; acc.y += v0.y; acc.z += v0.z; acc.w += v0.w;
    }
    // combine the two halves (lane l += lane l+16)
    acc.x += __shfl_down_sync(FULL, acc.x, 16);
    acc.y += __shfl_down_sync(FULL, acc.y, 16);
    acc.z += __shfl_down_sync(FULL, acc.z, 16);
    acc.w += __shfl_down_sync(FULL, acc.w, 16);
    if (lane < 16) {
        hbuf[w][l16 * 4 + 0] = fmaxf(acc.x + b1s[l16 * 4 + 0], 0.f);
        hbuf[w][l16 * 4 + 1] = fmaxf(acc.y + b1s[l16 * 4 + 1], 0.f);
        hbuf[w][l16 * 4 + 2] = fmaxf(acc.z + b1s[l16 * 4 + 2], 0.f);
        hbuf[w][l16 * 4 + 3] = fmaxf(acc.w + b1s[l16 * 4 + 3], 0.f);
    }
    __syncwarp();
    float h_lo = hbuf[w][lane];
    float h_hi = hbuf[w][lane + 32];
    int c = lane & 15;
    float accm = 0.f;
#pragma unroll
    for (int kk = 0; kk < 32; kk++) {
        float a = __shfl_sync(FULL, h_lo, kk);
        float b = __shfl_sync(FULL, h_hi, kk);
        float hk = half ? b : a;
        accm += hk * W2s[(half * 32 + kk) * 16 + c];
    }
    accm += __shfl_down_sync(FULL, accm, 16);
    if (lane < 16) g_g2[n * 16 + c] = accm;
}

// K_agg2: warp per node. 8 groups of 4 lanes each gather one edge's 16-float row via
// float4 (4 x 16B = 64B). Xor-reduce across groups, + b2, softmax, float4 store.
__global__ void k_agg2_fused(const float* __restrict__ b2, float4* __restrict__ out4) {
    int n    = (blockIdx.x * blockDim.x + threadIdx.x) >> 5;
    int lane = threadIdx.x & 31;
    if (n >= N_NODES) return;
    int grp = lane >> 2;   // 0..7 edge group
    int c4  = lane & 3;    // float4 column slot

    int start = g_offsets[n];
    int deg   = g_counts[n];
    const float4* g2v = (const float4*)g_g2;  // row = 4 float4
    float4 acc = make_float4(0.f, 0.f, 0.f, 0.f);
    for (int j = grp; j < deg; j += 8) {
        int s = __ldg(&g_edge_src[start + j]);
        float4 v = __ldg(&g2v[s * 4 + c4]);
        acc.x += v.x; acc.y += v.y; acc.z += v.z; acc.w += v.w;
    }
#pragma unroll
    for (int off = 16; off >= 4; off >>= 1) {
        acc.x += __shfl_xor_sync(FULL, acc.x, off);
        acc.y += __shfl_xor_sync(FULL, acc.y, off);
        acc.z += __shfl_xor_sync(FULL, acc.z, off);
        acc.w += __shfl_xor_sync(FULL, acc.w, off);
    }
    float x0 = acc.x + __ldg(&b2[c4 * 4 + 0]);
    float x1 = acc.y + __ldg(&b2[c4 * 4 + 1]);
    float x2 = acc.z + __ldg(&b2[c4 * 4 + 2]);
    float x3 = acc.w + __ldg(&b2[c4 * 4 + 3]);
    float m = fmaxf(fmaxf(x0, x1), fmaxf(x2, x3));
    m = fmaxf(m, __shfl_xor_sync(FULL, m, 1));
    m = fmaxf(m, __shfl_xor_sync(FULL, m, 2));
    float e0 = expf(x0 - m), e1 = expf(x1 - m), e2 = expf(x2 - m), e3 = expf(x3 - m);
    float s = e0 + e1 + e2 + e3;
    s += __shfl_xor_sync(FULL, s, 1);
    s += __shfl_xor_sync(FULL, s, 2);
    float inv = 1.f / s;
    if (lane < 4)
        out4[n * 4 + c4] = make_float4(e0 * inv, e1 * inv, e2 * inv, e3 * inv);
}

extern "C" void kernel_launch(void* const* d_in, const int* in_sizes, int n_in,
                              void* d_out, int out_size) {
    const float* feature = (const float*)d_in[0];
    const float* W1      = (const float*)d_in[1];
    const float* b1      = (const float*)d_in[2];
    const float* W2      = (const float*)d_in[3];
    const float* b2      = (const float*)d_in[4];
    const int*   src     = (const int*)d_in[5];
    const int*   dst     = (const int*)d_in[6];
    float4*      out4    = (float4*)d_out;
    int E = in_sizes[5];

    int rowBlocks = (N_NODES * 32 + 255) / 256;
    k1_gemm1<<<rowBlocks, 256>>>(feature, W1);

    k_hist<<<(E + 255) / 256, 256>>>(dst, E);
    k_passA<<<NB, 256>>>();
    k_passC<<<NB, 1024>>>();
    k_fill<<<(E + 255) / 256, 256>>>(src, dst, E);

    k_agg1_fused<<<rowBlocks, 256>>>(b1, W2);
    k_agg2_fused<<<(N_NODES * 32 + 255) / 256, 256>>>(b2, out4);
}